// round 5
// baseline (speedup 1.0000x reference)
#include <cuda_runtime.h>

// RotationGate: batched RX on qubit 0 (MSB axis) of a 22-qubit state.
// state_re/state_im: (DIM, 16) fp32 row-major; each row = 4 float4.
// out: (2, DIM, 16) fp32 (real plane, imag plane).
//   out0 = c*s0 - i*s*s1 ; out1 = c*s1 - i*s*s0  with c=cos(th/2), s=sin(th/2)
//
// HBM-bound streaming (1.07 GB). R4 (fused, no sync, MUFU coeffs) hit
// 150.2us / 85.8% DRAM. R5: 2 float4-groups per thread (t, t+256) --
// same batch-quad (256 % 4 == 0) so coefficients are computed once and
// reused; 8 front-batched LDG.128 per thread doubles in-flight bytes/SM
// and halves per-load instruction overhead.

#define DIM_    4194304L
#define BATCH_  16L
#define HALF4   ((DIM_ / 2) * BATCH_ / 4)   /* 8,388,608 float4 per half-plane */
#define IMOFF   (DIM_ * BATCH_ / 4)         /* 16,777,216 float4: imag plane  */

__global__ __launch_bounds__(256)
void rot_fused_kernel(const float* __restrict__ theta,
                      const float* __restrict__ re_,
                      const float* __restrict__ im_,
                      float* __restrict__ out_) {
    long t0 = (long)blockIdx.x * 512L + threadIdx.x;  // group A
    long t1 = t0 + 256L;                              // group B (same batch quad)
    const float4* __restrict__ re  = (const float4*)re_;
    const float4* __restrict__ im  = (const float4*)im_;
    float4* __restrict__ out = (float4*)out_;

    int g = (int)(threadIdx.x & 3);  // batch quad: batches 4g..4g+3
    float4 th = ((const float4*)theta)[g];

    // Front-batch all 8 bulk loads (MLP=8 per thread).
    float4 a_r0 = re[t0];
    float4 a_i0 = im[t0];
    float4 a_r1 = re[t0 + HALF4];
    float4 a_i1 = im[t0 + HALF4];
    float4 b_r0 = re[t1];
    float4 b_i0 = im[t1];
    float4 b_r1 = re[t1 + HALF4];
    float4 b_i1 = im[t1 + HALF4];

    float4 c4, s4;
    c4.x = __cosf(th.x * 0.5f);  s4.x = __sinf(th.x * 0.5f);
    c4.y = __cosf(th.y * 0.5f);  s4.y = __sinf(th.y * 0.5f);
    c4.z = __cosf(th.z * 0.5f);  s4.z = __sinf(th.z * 0.5f);
    c4.w = __cosf(th.w * 0.5f);  s4.w = __sinf(th.w * 0.5f);

    float4 o;

    // Group A
    o.x = fmaf(c4.x, a_r0.x,  s4.x * a_i1.x);
    o.y = fmaf(c4.y, a_r0.y,  s4.y * a_i1.y);
    o.z = fmaf(c4.z, a_r0.z,  s4.z * a_i1.z);
    o.w = fmaf(c4.w, a_r0.w,  s4.w * a_i1.w);
    out[t0] = o;

    o.x = fmaf(c4.x, a_r1.x,  s4.x * a_i0.x);
    o.y = fmaf(c4.y, a_r1.y,  s4.y * a_i0.y);
    o.z = fmaf(c4.z, a_r1.z,  s4.z * a_i0.z);
    o.w = fmaf(c4.w, a_r1.w,  s4.w * a_i0.w);
    out[t0 + HALF4] = o;

    o.x = fmaf(c4.x, a_i0.x, -s4.x * a_r1.x);
    o.y = fmaf(c4.y, a_i0.y, -s4.y * a_r1.y);
    o.z = fmaf(c4.z, a_i0.z, -s4.z * a_r1.z);
    o.w = fmaf(c4.w, a_i0.w, -s4.w * a_r1.w);
    out[t0 + IMOFF] = o;

    o.x = fmaf(c4.x, a_i1.x, -s4.x * a_r0.x);
    o.y = fmaf(c4.y, a_i1.y, -s4.y * a_r0.y);
    o.z = fmaf(c4.z, a_i1.z, -s4.z * a_r0.z);
    o.w = fmaf(c4.w, a_i1.w, -s4.w * a_r0.w);
    out[t0 + IMOFF + HALF4] = o;

    // Group B
    o.x = fmaf(c4.x, b_r0.x,  s4.x * b_i1.x);
    o.y = fmaf(c4.y, b_r0.y,  s4.y * b_i1.y);
    o.z = fmaf(c4.z, b_r0.z,  s4.z * b_i1.z);
    o.w = fmaf(c4.w, b_r0.w,  s4.w * b_i1.w);
    out[t1] = o;

    o.x = fmaf(c4.x, b_r1.x,  s4.x * b_i0.x);
    o.y = fmaf(c4.y, b_r1.y,  s4.y * b_i0.y);
    o.z = fmaf(c4.z, b_r1.z,  s4.z * b_i0.z);
    o.w = fmaf(c4.w, b_r1.w,  s4.w * b_i0.w);
    out[t1 + HALF4] = o;

    o.x = fmaf(c4.x, b_i0.x, -s4.x * b_r1.x);
    o.y = fmaf(c4.y, b_i0.y, -s4.y * b_r1.y);
    o.z = fmaf(c4.z, b_i0.z, -s4.z * b_r1.z);
    o.w = fmaf(c4.w, b_i0.w, -s4.w * b_r1.w);
    out[t1 + IMOFF] = o;

    o.x = fmaf(c4.x, b_i1.x, -s4.x * b_r0.x);
    o.y = fmaf(c4.y, b_i1.y, -s4.y * b_r0.y);
    o.z = fmaf(c4.z, b_i1.z, -s4.z * b_r0.z);
    o.w = fmaf(c4.w, b_i1.w, -s4.w * b_r0.w);
    out[t1 + IMOFF + HALF4] = o;
}

extern "C" void kernel_launch(void* const* d_in, const int* in_sizes, int n_in,
                              void* d_out, int out_size) {
    const float* theta = (const float*)d_in[0];
    const float* s_re  = (const float*)d_in[1];
    const float* s_im  = (const float*)d_in[2];
    float* out = (float*)d_out;

    long total  = HALF4 / 2;      // 4,194,304 threads (2 groups each)
    int  tpb    = 256;
    long blocks = total / tpb;    // 16,384 blocks
    rot_fused_kernel<<<(unsigned)blocks, tpb>>>(theta, s_re, s_im, out);
}

// round 6
// speedup vs baseline: 1.0002x; 1.0002x over previous
#include <cuda_runtime.h>

// RotationGate: batched RX on qubit 0 (MSB axis) of a 22-qubit state.
// state_re/state_im: (DIM, 16) fp32 row-major; each row = 4 float4.
// out: (2, DIM, 16) fp32 (real plane, imag plane).
//   out0 = c*s0 - i*s*s1 ; out1 = c*s1 - i*s*s0  with c=cos(th/2), s=sin(th/2)
//
// HBM-bound streaming (1.07 GB). Round history:
//  R1 prep+main:            main 152.8us, total 160.3 (2 nodes)
//  R2 fused+barrier+.cs:    main 155.8    (barrier gates stores)
//  R4 fused, no sync, MUFU: main 150.2us, total 157.7, DRAM 85.8%  <- best
//  R5 MLP=8/thread:         regs 43, occ 52.8% -> main 152.0 (occupancy trade)
// R6 = R4 structure + pure-int32 indexing (all offsets < 2^31) + 512 tpb.

#define HALF4   8388608    /* (DIM/2)*16/4 float4 per half-plane */
#define IMOFF   16777216   /* DIM*16/4: imag plane offset in float4 */

__global__ __launch_bounds__(512)
void rot_fused_kernel(const float* __restrict__ theta,
                      const float* __restrict__ re_,
                      const float* __restrict__ im_,
                      float* __restrict__ out_) {
    int t = blockIdx.x * 512 + threadIdx.x;   // t in [0, HALF4)
    const float4* __restrict__ re  = (const float4*)re_;
    const float4* __restrict__ im  = (const float4*)im_;
    float4* __restrict__ out = (float4*)out_;

    int g = threadIdx.x & 3;  // batch quad: batches 4g..4g+3
    float4 th = ((const float4*)theta)[g];

    // Front-batch the 4 bulk loads; MUFU coeff math overlaps DRAM latency.
    float4 r0 = re[t];
    float4 i0 = im[t];
    float4 r1 = re[t + HALF4];
    float4 i1 = im[t + HALF4];

    float4 c4, s4;
    c4.x = __cosf(th.x * 0.5f);  s4.x = __sinf(th.x * 0.5f);
    c4.y = __cosf(th.y * 0.5f);  s4.y = __sinf(th.y * 0.5f);
    c4.z = __cosf(th.z * 0.5f);  s4.z = __sinf(th.z * 0.5f);
    c4.w = __cosf(th.w * 0.5f);  s4.w = __sinf(th.w * 0.5f);

    float4 o0r, o0i, o1r, o1i;

    o0r.x = fmaf(c4.x, r0.x,  s4.x * i1.x);
    o0r.y = fmaf(c4.y, r0.y,  s4.y * i1.y);
    o0r.z = fmaf(c4.z, r0.z,  s4.z * i1.z);
    o0r.w = fmaf(c4.w, r0.w,  s4.w * i1.w);

    o0i.x = fmaf(c4.x, i0.x, -s4.x * r1.x);
    o0i.y = fmaf(c4.y, i0.y, -s4.y * r1.y);
    o0i.z = fmaf(c4.z, i0.z, -s4.z * r1.z);
    o0i.w = fmaf(c4.w, i0.w, -s4.w * r1.w);

    o1r.x = fmaf(c4.x, r1.x,  s4.x * i0.x);
    o1r.y = fmaf(c4.y, r1.y,  s4.y * i0.y);
    o1r.z = fmaf(c4.z, r1.z,  s4.z * i0.z);
    o1r.w = fmaf(c4.w, r1.w,  s4.w * i0.w);

    o1i.x = fmaf(c4.x, i1.x, -s4.x * r0.x);
    o1i.y = fmaf(c4.y, i1.y, -s4.y * r0.y);
    o1i.z = fmaf(c4.z, i1.z, -s4.z * r0.z);
    o1i.w = fmaf(c4.w, i1.w, -s4.w * r0.w);

    out[t]                 = o0r;
    out[t + HALF4]         = o1r;
    out[t + IMOFF]         = o0i;
    out[t + IMOFF + HALF4] = o1i;
}

extern "C" void kernel_launch(void* const* d_in, const int* in_sizes, int n_in,
                              void* d_out, int out_size) {
    const float* theta = (const float*)d_in[0];
    const float* s_re  = (const float*)d_in[1];
    const float* s_im  = (const float*)d_in[2];
    float* out = (float*)d_out;

    int tpb    = 512;
    int blocks = HALF4 / tpb;     // 16,384 blocks
    rot_fused_kernel<<<blocks, tpb>>>(theta, s_re, s_im, out);
}

// round 7
// speedup vs baseline: 1.0004x; 1.0002x over previous
#include <cuda_runtime.h>

// RotationGate: batched RX on qubit 0 (MSB axis) of a 22-qubit state.
// state_re/state_im: (DIM, 16) fp32 row-major; each row = 4 float4.
// out: (2, DIM, 16) fp32 (real plane, imag plane).
//   out0 = c*s0 - i*s*s1 ; out1 = c*s1 - i*s*s0  with c=cos(th/2), s=sin(th/2)
//
// HBM-bound streaming (1.07 GB). Round history:
//  R1 prep+main:            main 152.8us, total 160.3 (2 graph nodes)
//  R2 fused+barrier+.cs:    main 155.8    (barrier gates stores)
//  R4 fused, no-sync, MUFU: main 150.2us, total 157.7, DRAM 85.8%, occ 82.5%
//  R5 MLP=8/thread:         occ 52.8 -> main 152.0 (occupancy trade, reverted)
//  R6 tpb=512 + int32:      main 150.9, occ 73.3 (neutral)
// R7 = R4 launch shape (tpb=256, lb(256,8)) + int32 indexing + store-on-ready.
// Plateau evidence: ~6.75-6.8 TB/s (85% spec) for this 4R+4W fp32 stream mix.

#define HALF4   8388608    /* (DIM/2)*16/4 float4 per half-plane */
#define IMOFF   16777216   /* DIM*16/4: imag plane offset in float4 */

__global__ __launch_bounds__(256, 8)
void rot_fused_kernel(const float* __restrict__ theta,
                      const float* __restrict__ re_,
                      const float* __restrict__ im_,
                      float* __restrict__ out_) {
    int t = blockIdx.x * 256 + threadIdx.x;   // t in [0, HALF4)
    const float4* __restrict__ re  = (const float4*)re_;
    const float4* __restrict__ im  = (const float4*)im_;
    float4* __restrict__ out = (float4*)out_;

    int g = threadIdx.x & 3;  // batch quad: batches 4g..4g+3
    float4 th = ((const float4*)theta)[g];

    // Front-batch the 4 bulk loads; MUFU coeff math overlaps DRAM latency.
    float4 r0 = re[t];
    float4 i0 = im[t];
    float4 r1 = re[t + HALF4];
    float4 i1 = im[t + HALF4];

    float4 c4, s4;
    c4.x = __cosf(th.x * 0.5f);  s4.x = __sinf(th.x * 0.5f);
    c4.y = __cosf(th.y * 0.5f);  s4.y = __sinf(th.y * 0.5f);
    c4.z = __cosf(th.z * 0.5f);  s4.z = __sinf(th.z * 0.5f);
    c4.w = __cosf(th.w * 0.5f);  s4.w = __sinf(th.w * 0.5f);

    float4 o;

    // Store each result as soon as it is ready: first STG issues ~20cy
    // earlier and register live ranges stay short (regs <= 32).
    o.x = fmaf(c4.x, r0.x,  s4.x * i1.x);
    o.y = fmaf(c4.y, r0.y,  s4.y * i1.y);
    o.z = fmaf(c4.z, r0.z,  s4.z * i1.z);
    o.w = fmaf(c4.w, r0.w,  s4.w * i1.w);
    out[t] = o;

    o.x = fmaf(c4.x, r1.x,  s4.x * i0.x);
    o.y = fmaf(c4.y, r1.y,  s4.y * i0.y);
    o.z = fmaf(c4.z, r1.z,  s4.z * i0.z);
    o.w = fmaf(c4.w, r1.w,  s4.w * i0.w);
    out[t + HALF4] = o;

    o.x = fmaf(c4.x, i0.x, -s4.x * r1.x);
    o.y = fmaf(c4.y, i0.y, -s4.y * r1.y);
    o.z = fmaf(c4.z, i0.z, -s4.z * r1.z);
    o.w = fmaf(c4.w, i0.w, -s4.w * r1.w);
    out[t + IMOFF] = o;

    o.x = fmaf(c4.x, i1.x, -s4.x * r0.x);
    o.y = fmaf(c4.y, i1.y, -s4.y * r0.y);
    o.z = fmaf(c4.z, i1.z, -s4.z * r0.z);
    o.w = fmaf(c4.w, i1.w, -s4.w * r0.w);
    out[t + IMOFF + HALF4] = o;
}

extern "C" void kernel_launch(void* const* d_in, const int* in_sizes, int n_in,
                              void* d_out, int out_size) {
    const float* theta = (const float*)d_in[0];
    const float* s_re  = (const float*)d_in[1];
    const float* s_im  = (const float*)d_in[2];
    float* out = (float*)d_out;

    int tpb    = 256;
    int blocks = HALF4 / tpb;     // 32,768 blocks
    rot_fused_kernel<<<blocks, tpb>>>(theta, s_re, s_im, out);
}